// round 14
// baseline (speedup 1.0000x reference)
#include <cuda_runtime.h>

// Problem constants
#define Bsz 4096
#define Vn  50
#define Fn  15
#define Hn  256
#define Gn  1024   // 4*H

// ---------------- scratch (static device globals; no allocation) ----------
__device__ float g_h1a[Bsz * Hn];
__device__ float g_h1b[Bsz * Hn];
__device__ float g_c1 [Bsz * Hn];
__device__ float g_h2a[Bsz * Hn];
__device__ float g_h2b[Bsz * Hn];
__device__ float g_c2 [Bsz * Hn];
__device__ float g_m1[Bsz * 1024];
__device__ float g_m2[Bsz * 1024];
__device__ float g_m3[Bsz * 512];
__device__ float g_m4[Bsz * 256];
__device__ float g_pre2[Bsz * Gn];

typedef unsigned long long ull;

__device__ __forceinline__ void dup2(ull& d, float s) {
    asm("mov.b64 %0,{%1,%1};" : "=l"(d) : "f"(s));
}
__device__ __forceinline__ void ffma2(ull& d, ull a, ull b) {
    asm("fma.rn.f32x2 %0,%1,%2,%0;" : "+l"(d) : "l"(a), "l"(b));
}
__device__ __forceinline__ float2 u2f(ull u) {
    float2 f; asm("mov.b64 {%0,%1},%2;" : "=f"(f.x), "=f"(f.y) : "l"(u)); return f;
}
// Fast-math gates — validated (round 11/13: rel_err ~7e-6 end-to-end).
__device__ __forceinline__ float fsig(float x) {
    return __fdividef(1.0f, 1.0f + __expf(-x));
}
__device__ __forceinline__ float ftanh(float x) {
    return 1.0f - __fdividef(2.0f, __expf(2.0f * x) + 1.0f);
}

// ---------------- zero the recurrent states --------------------------------
__global__ void zero_states_kernel() {
    int idx = blockIdx.x * blockDim.x + threadIdx.x;
    if (idx < Bsz * Hn) {
        g_h1a[idx] = 0.f; g_c1[idx] = 0.f;
        g_h2a[idx] = 0.f; g_c2[idx] = 0.f;
    }
}

// ---------------- fused SGEMM (f32x2, DUP-A smem, K-tile 16) ----------------
// Block tile 128x128, 256 threads, quadrant 8x8 microtile.
// A is stored DUPLICATED in smem (As[kk][2m]=As[kk][2m+1]=a) so the f32x2
// broadcast operand is loaded directly as a ready 64-bit pair — removes the
// per-kk mov.b64 duplication (~30% of inner-loop issue slots in round 13).
// A loads stay broadcast across tx (conflict-free). B path unchanged.
// smem: As 32KB + Bs 16KB = 48KB static, 2 CTAs/SM.
// REMAP: weight row = ((n&3)<<8)|(n>>2). EPI: 0 bias, 1 relu, 2 LSTM update.
template <int EPI, int REMAP, int W4>
__global__ void __launch_bounds__(256, 2) gemm4(
    const float* __restrict__ A,  int lda,
    const float* __restrict__ W,  int ldw, int K,
    const float* __restrict__ A2, int lda2,
    const float* __restrict__ W2, int ldw2, int K2,
    const float* __restrict__ b1, const float* __restrict__ b2,
    const float* __restrict__ addmat,
    float* __restrict__ C, int N,
    float* __restrict__ cSt)
{
    __shared__ __align__(16) float As[2][16][256];   // duplicated A
    __shared__ __align__(16) float Bs[2][16][128];

    const int tid = threadIdx.x;
    const int tx = tid & 15;
    const int ty = tid >> 4;
    const int m0 = blockIdx.y * 128;
    const int n0 = blockIdx.x * 128;

    const int lr = tid >> 1;        // 0..127
    const int lc = (tid & 1) * 8;   // 0 or 8
    const int gn = n0 + lr;
    const int wrow = REMAP ? (((gn & 3) << 8) | (gn >> 2)) : gn;
    const float* Ap = A + (size_t)(m0 + lr) * lda + lc;
    const float* Wp = W + (size_t)wrow * ldw + lc;

    ull acc[8][4];
#pragma unroll
    for (int i = 0; i < 8; i++)
#pragma unroll
        for (int j = 0; j < 4; j++) acc[i][j] = 0ull;

    // ---- preload stage 0 ----
    {
        float4 a0 = *(const float4*)Ap;
        float4 a1 = *(const float4*)(Ap + 4);
        float4 w0, w1;
        if (W4) { w0 = *(const float4*)Wp; w1 = *(const float4*)(Wp + 4); }
        else {
            w0 = make_float4(Wp[0], Wp[1], Wp[2], Wp[3]);
            w1 = make_float4(Wp[4], Wp[5], Wp[6], Wp[7]);
        }
        float av[8] = {a0.x, a0.y, a0.z, a0.w, a1.x, a1.y, a1.z, a1.w};
#pragma unroll
        for (int i = 0; i < 8; i++) {
            ull d; dup2(d, av[i]);
            *(ull*)&As[0][lc + i][2 * lr] = d;
        }
        Bs[0][lc + 0][lr] = w0.x; Bs[0][lc + 1][lr] = w0.y;
        Bs[0][lc + 2][lr] = w0.z; Bs[0][lc + 3][lr] = w0.w;
        Bs[0][lc + 4][lr] = w1.x; Bs[0][lc + 5][lr] = w1.y;
        Bs[0][lc + 6][lr] = w1.z; Bs[0][lc + 7][lr] = w1.w;
    }
    __syncthreads();

    int cur = 0;
    for (int k0 = 0; k0 < K; k0 += 16) {
        const bool more = (k0 + 16) < K;
        float4 pa0, pa1, pw0, pw1;
        if (more) {
            pa0 = *(const float4*)(Ap + k0 + 16);
            pa1 = *(const float4*)(Ap + k0 + 20);
            const float* wq = Wp + k0 + 16;
            if (W4) { pw0 = *(const float4*)wq; pw1 = *(const float4*)(wq + 4); }
            else {
                pw0 = make_float4(wq[0], wq[1], wq[2], wq[3]);
                pw1 = make_float4(wq[4], wq[5], wq[6], wq[7]);
            }
        }
#pragma unroll
        for (int kk = 0; kk < 16; kk++) {
            ulonglong2 aq0 = *(const ulonglong2*)&As[cur][kk][8 * ty];
            ulonglong2 aq1 = *(const ulonglong2*)&As[cur][kk][8 * ty + 4];
            ulonglong2 aq2 = *(const ulonglong2*)&As[cur][kk][128 + 8 * ty];
            ulonglong2 aq3 = *(const ulonglong2*)&As[cur][kk][128 + 8 * ty + 4];
            ulonglong2 bq0 = *(const ulonglong2*)&Bs[cur][kk][tx * 4];
            ulonglong2 bq1 = *(const ulonglong2*)&Bs[cur][kk][64 + tx * 4];
            ull av[8] = {aq0.x, aq0.y, aq1.x, aq1.y, aq2.x, aq2.y, aq3.x, aq3.y};
#pragma unroll
            for (int i = 0; i < 8; i++) {
                ffma2(acc[i][0], av[i], bq0.x);
                ffma2(acc[i][1], av[i], bq0.y);
                ffma2(acc[i][2], av[i], bq1.x);
                ffma2(acc[i][3], av[i], bq1.y);
            }
        }
        if (more) {
            int nx = cur ^ 1;
            float av2[8] = {pa0.x, pa0.y, pa0.z, pa0.w, pa1.x, pa1.y, pa1.z, pa1.w};
#pragma unroll
            for (int i = 0; i < 8; i++) {
                ull d; dup2(d, av2[i]);
                *(ull*)&As[nx][lc + i][2 * lr] = d;
            }
            Bs[nx][lc + 0][lr] = pw0.x; Bs[nx][lc + 1][lr] = pw0.y;
            Bs[nx][lc + 2][lr] = pw0.z; Bs[nx][lc + 3][lr] = pw0.w;
            Bs[nx][lc + 4][lr] = pw1.x; Bs[nx][lc + 5][lr] = pw1.y;
            Bs[nx][lc + 6][lr] = pw1.z; Bs[nx][lc + 7][lr] = pw1.w;
        }
        __syncthreads();
        cur ^= 1;
    }

    // ---- small-K tail (x_v @ Wih_x.T, K2 <= 15) ----
    if (K2 > 0) {
        float (*Ta)[256] = (float(*)[256]) & As[0][0][0];
        float (*Tb)[128] = (float(*)[128]) & Bs[0][0][0];
        for (int idx = tid; idx < 128 * K2; idx += 256) {
            int m = idx & 127;
            int k = idx >> 7;
            float va = A2[(size_t)(m0 + m) * lda2 + k];
            Ta[k][2 * m] = va;
            Ta[k][2 * m + 1] = va;
            int g2 = n0 + m;
            int wr2 = REMAP ? (((g2 & 3) << 8) | (g2 >> 2)) : g2;
            Tb[k][m] = W2[(size_t)wr2 * ldw2 + k];
        }
        __syncthreads();
        for (int kk = 0; kk < K2; kk++) {
            ulonglong2 aq0 = *(const ulonglong2*)&Ta[kk][8 * ty];
            ulonglong2 aq1 = *(const ulonglong2*)&Ta[kk][8 * ty + 4];
            ulonglong2 aq2 = *(const ulonglong2*)&Ta[kk][128 + 8 * ty];
            ulonglong2 aq3 = *(const ulonglong2*)&Ta[kk][128 + 8 * ty + 4];
            ulonglong2 bq0 = *(const ulonglong2*)&Tb[kk][tx * 4];
            ulonglong2 bq1 = *(const ulonglong2*)&Tb[kk][64 + tx * 4];
            ull av[8] = {aq0.x, aq0.y, aq1.x, aq1.y, aq2.x, aq2.y, aq3.x, aq3.y};
#pragma unroll
            for (int i = 0; i < 8; i++) {
                ffma2(acc[i][0], av[i], bq0.x);
                ffma2(acc[i][1], av[i], bq0.y);
                ffma2(acc[i][2], av[i], bq1.x);
                ffma2(acc[i][3], av[i], bq1.y);
            }
        }
    }

    // ---- epilogue ----
    float add[8];
    if (EPI != 2 || addmat == nullptr) {
#pragma unroll
        for (int j = 0; j < 8; j++) {
            int n = n0 + ((j < 4) ? (4 * tx + j) : (64 + 4 * tx + (j - 4)));
            int rn = REMAP ? (((n & 3) << 8) | (n >> 2)) : n;
            float t = 0.f;
            if (b1) t += b1[rn];
            if (b2) t += b2[rn];
            add[j] = t;
        }
    }

    if (EPI == 2) {
        const int hu0 = (n0 >> 2) + tx;
        const int hu1 = hu0 + 16;
#pragma unroll
        for (int i = 0; i < 8; i++) {
            int m = m0 + ((i < 4) ? (4 * ty + i) : (64 + 4 * ty + (i - 4)));
            float g[8];
#pragma unroll
            for (int j4 = 0; j4 < 4; j4++) {
                float2 f = u2f(acc[i][j4]);
                g[2 * j4] = f.x; g[2 * j4 + 1] = f.y;
            }
            if (addmat) {
                float4 p0 = *(const float4*)(addmat + (size_t)m * Gn + n0 + 4 * tx);
                float4 p1 = *(const float4*)(addmat + (size_t)m * Gn + n0 + 64 + 4 * tx);
                g[0] += p0.x; g[1] += p0.y; g[2] += p0.z; g[3] += p0.w;
                g[4] += p1.x; g[5] += p1.y; g[6] += p1.z; g[7] += p1.w;
            } else {
#pragma unroll
                for (int j = 0; j < 8; j++) g[j] += add[j];
            }
            size_t c0i = (size_t)m * Hn + hu0;
            size_t c1i = (size_t)m * Hn + hu1;
            {
                float iv = fsig(g[0]), fv = fsig(g[1]);
                float gv = ftanh(g[2]), ov = fsig(g[3]);
                float cn = fv * cSt[c0i] + iv * gv;
                cSt[c0i] = cn;
                C[c0i] = ov * ftanh(cn);
            }
            {
                float iv = fsig(g[4]), fv = fsig(g[5]);
                float gv = ftanh(g[6]), ov = fsig(g[7]);
                float cn = fv * cSt[c1i] + iv * gv;
                cSt[c1i] = cn;
                C[c1i] = ov * ftanh(cn);
            }
        }
    } else {
#pragma unroll
        for (int i = 0; i < 8; i++) {
            int m = m0 + ((i < 4) ? (4 * ty + i) : (64 + 4 * ty + (i - 4)));
            float o[8];
#pragma unroll
            for (int j4 = 0; j4 < 4; j4++) {
                float2 f = u2f(acc[i][j4]);
                o[2 * j4]     = f.x + add[2 * j4];
                o[2 * j4 + 1] = f.y + add[2 * j4 + 1];
            }
            if (EPI == 1) {
#pragma unroll
                for (int j = 0; j < 8; j++) o[j] = fmaxf(o[j], 0.f);
            }
            *(float4*)(C + (size_t)m * N + n0 + 4 * tx)      = make_float4(o[0], o[1], o[2], o[3]);
            *(float4*)(C + (size_t)m * N + n0 + 64 + 4 * tx) = make_float4(o[4], o[5], o[6], o[7]);
        }
    }
}

// ---------------- pi head: out[b][v] = tanh(h2[b]·piW + pib) ----------------
__global__ void pi_kernel(const float* __restrict__ h2,
                          const float* __restrict__ piW,
                          const float* __restrict__ pib,
                          float* __restrict__ out, int v) {
    int gw = (blockIdx.x * blockDim.x + threadIdx.x) >> 5;
    int lane = threadIdx.x & 31;
    if (gw >= Bsz) return;
    const float* hr = h2 + (size_t)gw * Hn;
    float s = 0.f;
#pragma unroll
    for (int k = lane; k < Hn; k += 32) s += hr[k] * piW[k];
#pragma unroll
    for (int off = 16; off > 0; off >>= 1)
        s += __shfl_down_sync(0xffffffffu, s, off);
    if (lane == 0)
        out[(size_t)gw * Vn + v] = ftanh(s + pib[0]);
}

// ---------------- launch ----------------------------------------------------
extern "C" void kernel_launch(void* const* d_in, const int* in_sizes, int n_in,
                              void* d_out, int out_size) {
    const float* state  = (const float*)d_in[0];   // [4096, 750]
    const float* l1_Wih = (const float*)d_in[1];   // [1024, 15]
    const float* l1_Whh = (const float*)d_in[2];   // [1024, 256]
    const float* l1_bih = (const float*)d_in[3];
    const float* l1_bhh = (const float*)d_in[4];
    const float* fc1_W  = (const float*)d_in[5];   // [1024, 256]
    const float* fc1_b  = (const float*)d_in[6];
    const float* fc2_W  = (const float*)d_in[7];   // [1024, 1024]
    const float* fc2_b  = (const float*)d_in[8];
    const float* fc3_W  = (const float*)d_in[9];   // [512, 1024]
    const float* fc3_b  = (const float*)d_in[10];
    const float* fc4_W  = (const float*)d_in[11];  // [256, 512]
    const float* fc4_b  = (const float*)d_in[12];
    const float* l2_Wih = (const float*)d_in[13];  // [1024, 271]
    const float* l2_Whh = (const float*)d_in[14];  // [1024, 256]
    const float* l2_bih = (const float*)d_in[15];
    const float* l2_bhh = (const float*)d_in[16];
    const float* pi_W   = (const float*)d_in[17];  // [1, 256]
    const float* pi_b   = (const float*)d_in[18];  // [1]
    float* out = (float*)d_out;                    // [4096, 50]

    float *h1a, *h1b, *c1, *h2a, *h2b, *c2, *m1, *m2, *m3, *m4, *pre2;
    cudaGetSymbolAddress((void**)&h1a, g_h1a);
    cudaGetSymbolAddress((void**)&h1b, g_h1b);
    cudaGetSymbolAddress((void**)&c1,  g_c1);
    cudaGetSymbolAddress((void**)&h2a, g_h2a);
    cudaGetSymbolAddress((void**)&h2b, g_h2b);
    cudaGetSymbolAddress((void**)&c2,  g_c2);
    cudaGetSymbolAddress((void**)&m1, g_m1);
    cudaGetSymbolAddress((void**)&m2, g_m2);
    cudaGetSymbolAddress((void**)&m3, g_m3);
    cudaGetSymbolAddress((void**)&m4, g_m4);
    cudaGetSymbolAddress((void**)&pre2, g_pre2);

    zero_states_kernel<<<(Bsz * Hn + 255) / 256, 256>>>();

    dim3 sgrid(Gn / 128, Bsz / 128);   // 8 x 32

    // ---- LSTM1 scan (fused gate GEMM + cell update), ping-pong h ----
    for (int v = 0; v < Vn; v++) {
        const float* hin  = (v & 1) ? h1b : h1a;
        float*       hout = (v & 1) ? h1a : h1b;
        gemm4<2, 1, 1><<<sgrid, 256>>>(
            hin, Hn, l1_Whh, Hn, Hn,
            state + v * Fn, Vn * Fn, l1_Wih, Fn, Fn,
            l1_bih, l1_bhh, nullptr,
            hout, Gn, c1);
    }
    const float* h1fin = (Vn & 1) ? h1b : h1a;

    // ---- MLP stack (relu) ----
    gemm4<1, 0, 1><<<dim3(1024 / 128, 32), 256>>>(
        h1fin, Hn, fc1_W, Hn, Hn,
        nullptr, 0, nullptr, 0, 0,
        fc1_b, nullptr, nullptr, m1, 1024, nullptr);
    gemm4<1, 0, 1><<<dim3(1024 / 128, 32), 256>>>(
        m1, 1024, fc2_W, 1024, 1024,
        nullptr, 0, nullptr, 0, 0,
        fc2_b, nullptr, nullptr, m2, 1024, nullptr);
    gemm4<1, 0, 1><<<dim3(512 / 128, 32), 256>>>(
        m2, 1024, fc3_W, 1024, 1024,
        nullptr, 0, nullptr, 0, 0,
        fc3_b, nullptr, nullptr, m3, 512, nullptr);
    gemm4<1, 0, 1><<<dim3(256 / 128, 32), 256>>>(
        m3, 512, fc4_W, 512, 512,
        nullptr, 0, nullptr, 0, 0,
        fc4_b, nullptr, nullptr, m4, 256, nullptr);

    // ---- pre2 = m4 @ Wih2[:,15:].T + bih + bhh  (REMAPPED quadrant layout) --
    gemm4<0, 1, 0><<<sgrid, 256>>>(
        m4, 256, l2_Wih + 15, 271, 256,
        nullptr, 0, nullptr, 0, 0,
        l2_bih, l2_bhh, nullptr, pre2, Gn, nullptr);

    // ---- LSTM2 scan (fused) + pi head, ping-pong h ----
    for (int v = 0; v < Vn; v++) {
        const float* hin  = (v & 1) ? h2b : h2a;
        float*       hout = (v & 1) ? h2a : h2b;
        gemm4<2, 1, 1><<<sgrid, 256>>>(
            hin, Hn, l2_Whh, Hn, Hn,
            state + v * Fn, Vn * Fn, l2_Wih, 271, Fn,
            nullptr, nullptr, pre2,
            hout, Gn, c2);
        pi_kernel<<<Bsz / 8, 256>>>(hout, pi_W, pi_b, out, v);
    }
}

// round 15
// speedup vs baseline: 1.3908x; 1.3908x over previous
#include <cuda_runtime.h>

// Problem constants
#define Bsz 4096
#define Vn  50
#define Fn  15
#define Hn  256
#define Gn  1024   // 4*H

// ---------------- scratch (static device globals; no allocation) ----------
__device__ float g_h1a[Bsz * Hn];
__device__ float g_h1b[Bsz * Hn];
__device__ float g_c1 [Bsz * Hn];
__device__ float g_h2a[Bsz * Hn];
__device__ float g_h2b[Bsz * Hn];
__device__ float g_c2 [Bsz * Hn];
__device__ float g_m1[Bsz * 1024];
__device__ float g_m2[Bsz * 1024];
__device__ float g_m3[Bsz * 512];
__device__ float g_m4[Bsz * 256];
__device__ float g_pre2[Bsz * Gn];
// pi-head partial dot-products: [parity][bx=8][m=4096]
__device__ float g_pipart[2][8][Bsz];

typedef unsigned long long ull;

__device__ __forceinline__ void dup2(ull& d, float s) {
    asm("mov.b64 %0,{%1,%1};" : "=l"(d) : "f"(s));
}
__device__ __forceinline__ void ffma2(ull& d, ull a, ull b) {
    asm("fma.rn.f32x2 %0,%1,%2,%0;" : "+l"(d) : "l"(a), "l"(b));
}
__device__ __forceinline__ float2 u2f(ull u) {
    float2 f; asm("mov.b64 {%0,%1},%2;" : "=f"(f.x), "=f"(f.y) : "l"(u)); return f;
}
// Fast-math gates — validated (rounds 11/13: rel_err ~7e-6 end-to-end).
__device__ __forceinline__ float fsig(float x) {
    return __fdividef(1.0f, 1.0f + __expf(-x));
}
__device__ __forceinline__ float ftanh(float x) {
    return 1.0f - __fdividef(2.0f, __expf(2.0f * x) + 1.0f);
}

// ---------------- zero the recurrent states --------------------------------
__global__ void zero_states_kernel() {
    int idx = blockIdx.x * blockDim.x + threadIdx.x;
    if (idx < Bsz * Hn) {
        g_h1a[idx] = 0.f; g_c1[idx] = 0.f;
        g_h2a[idx] = 0.f; g_c2[idx] = 0.f;
    }
}

// ---------------- fused SGEMM (round-13 proven body + pi fusion) ------------
// Block tile 128x128, 256 threads, quadrant 8x8 microtile, f32x2 FMA.
// REMAP: weight row = ((n&3)<<8)|(n>>2): 4-col quadrant = one unit's {i,f,g,o}.
// EPI: 0 bias store, 1 relu store, 2 LSTM update, 3 LSTM update + pi partial
//      (+ finalize previous step's pi output in bx==0 CTAs).
template <int EPI, int REMAP, int W4>
__global__ void __launch_bounds__(256, 2) gemm3(
    const float* __restrict__ A,  int lda,
    const float* __restrict__ W,  int ldw, int K,
    const float* __restrict__ A2, int lda2,
    const float* __restrict__ W2, int ldw2, int K2,
    const float* __restrict__ b1, const float* __restrict__ b2,
    const float* __restrict__ addmat,
    float* __restrict__ C, int N,
    float* __restrict__ cSt,
    const float* __restrict__ piW, const float* __restrict__ pib,
    float* __restrict__ outv,
    float* __restrict__ partCur, const float* __restrict__ partPrev,
    int vprev)
{
    __shared__ float As[2][16][128];
    __shared__ float Bs[2][16][128];

    const int tid = threadIdx.x;
    const int tx = tid & 15;
    const int ty = tid >> 4;
    const int m0 = blockIdx.y * 128;
    const int n0 = blockIdx.x * 128;

    // ---- finalize previous step's pi output (bx==0 CTAs, independent) ----
    if (EPI == 3 && blockIdx.x == 0 && vprev >= 0 && tid < 128) {
        int m = m0 + tid;
        float s = pib[0];
#pragma unroll
        for (int b = 0; b < 8; b++) s += partPrev[b * Bsz + m];
        outv[(size_t)m * Vn + vprev] = ftanh(s);
    }

    const int lr = tid >> 1;        // 0..127
    const int lc = (tid & 1) * 8;   // 0 or 8
    const int gn = n0 + lr;
    const int wrow = REMAP ? (((gn & 3) << 8) | (gn >> 2)) : gn;
    const float* Ap = A + (size_t)(m0 + lr) * lda + lc;
    const float* Wp = W + (size_t)wrow * ldw + lc;

    ull acc[8][4];
#pragma unroll
    for (int i = 0; i < 8; i++)
#pragma unroll
        for (int j = 0; j < 4; j++) acc[i][j] = 0ull;

    // ---- preload stage 0 ----
    {
        float4 a0 = *(const float4*)Ap;
        float4 a1 = *(const float4*)(Ap + 4);
        float4 w0, w1;
        if (W4) { w0 = *(const float4*)Wp; w1 = *(const float4*)(Wp + 4); }
        else {
            w0 = make_float4(Wp[0], Wp[1], Wp[2], Wp[3]);
            w1 = make_float4(Wp[4], Wp[5], Wp[6], Wp[7]);
        }
        As[0][lc + 0][lr] = a0.x; As[0][lc + 1][lr] = a0.y;
        As[0][lc + 2][lr] = a0.z; As[0][lc + 3][lr] = a0.w;
        As[0][lc + 4][lr] = a1.x; As[0][lc + 5][lr] = a1.y;
        As[0][lc + 6][lr] = a1.z; As[0][lc + 7][lr] = a1.w;
        Bs[0][lc + 0][lr] = w0.x; Bs[0][lc + 1][lr] = w0.y;
        Bs[0][lc + 2][lr] = w0.z; Bs[0][lc + 3][lr] = w0.w;
        Bs[0][lc + 4][lr] = w1.x; Bs[0][lc + 5][lr] = w1.y;
        Bs[0][lc + 6][lr] = w1.z; Bs[0][lc + 7][lr] = w1.w;
    }
    __syncthreads();

    int cur = 0;
    for (int k0 = 0; k0 < K; k0 += 16) {
        const bool more = (k0 + 16) < K;
        float4 pa0, pa1, pw0, pw1;
        if (more) {
            pa0 = *(const float4*)(Ap + k0 + 16);
            pa1 = *(const float4*)(Ap + k0 + 20);
            const float* wq = Wp + k0 + 16;
            if (W4) { pw0 = *(const float4*)wq; pw1 = *(const float4*)(wq + 4); }
            else {
                pw0 = make_float4(wq[0], wq[1], wq[2], wq[3]);
                pw1 = make_float4(wq[4], wq[5], wq[6], wq[7]);
            }
        }
#pragma unroll
        for (int kk = 0; kk < 16; kk++) {
            float4 a0 = *(const float4*)&As[cur][kk][ty * 4];
            float4 a1 = *(const float4*)&As[cur][kk][64 + ty * 4];
            ulonglong2 bq0 = *(const ulonglong2*)&Bs[cur][kk][tx * 4];
            ulonglong2 bq1 = *(const ulonglong2*)&Bs[cur][kk][64 + tx * 4];
            float ar[8] = {a0.x, a0.y, a0.z, a0.w, a1.x, a1.y, a1.z, a1.w};
#pragma unroll
            for (int i = 0; i < 8; i++) {
                ull aa; dup2(aa, ar[i]);
                ffma2(acc[i][0], aa, bq0.x);
                ffma2(acc[i][1], aa, bq0.y);
                ffma2(acc[i][2], aa, bq1.x);
                ffma2(acc[i][3], aa, bq1.y);
            }
        }
        if (more) {
            int nx = cur ^ 1;
            As[nx][lc + 0][lr] = pa0.x; As[nx][lc + 1][lr] = pa0.y;
            As[nx][lc + 2][lr] = pa0.z; As[nx][lc + 3][lr] = pa0.w;
            As[nx][lc + 4][lr] = pa1.x; As[nx][lc + 5][lr] = pa1.y;
            As[nx][lc + 6][lr] = pa1.z; As[nx][lc + 7][lr] = pa1.w;
            Bs[nx][lc + 0][lr] = pw0.x; Bs[nx][lc + 1][lr] = pw0.y;
            Bs[nx][lc + 2][lr] = pw0.z; Bs[nx][lc + 3][lr] = pw0.w;
            Bs[nx][lc + 4][lr] = pw1.x; Bs[nx][lc + 5][lr] = pw1.y;
            Bs[nx][lc + 6][lr] = pw1.z; Bs[nx][lc + 7][lr] = pw1.w;
        }
        __syncthreads();
        cur ^= 1;
    }

    // ---- small-K tail (x_v @ Wih_x.T, K2 <= 15) ----
    if (K2 > 0) {
        float (*Ta)[128] = (float(*)[128]) & As[0][0][0];
        float (*Tb)[128] = (float(*)[128]) & Bs[0][0][0];
        for (int idx = tid; idx < 128 * K2; idx += 256) {
            int m = idx & 127;
            int k = idx >> 7;
            Ta[k][m] = A2[(size_t)(m0 + m) * lda2 + k];
            int g2 = n0 + m;
            int wr2 = REMAP ? (((g2 & 3) << 8) | (g2 >> 2)) : g2;
            Tb[k][m] = W2[(size_t)wr2 * ldw2 + k];
        }
        __syncthreads();
        for (int kk = 0; kk < K2; kk++) {
            float4 a0 = *(const float4*)&Ta[kk][ty * 4];
            float4 a1 = *(const float4*)&Ta[kk][64 + ty * 4];
            ulonglong2 bq0 = *(const ulonglong2*)&Tb[kk][tx * 4];
            ulonglong2 bq1 = *(const ulonglong2*)&Tb[kk][64 + tx * 4];
            float ar[8] = {a0.x, a0.y, a0.z, a0.w, a1.x, a1.y, a1.z, a1.w};
#pragma unroll
            for (int i = 0; i < 8; i++) {
                ull aa; dup2(aa, ar[i]);
                ffma2(acc[i][0], aa, bq0.x);
                ffma2(acc[i][1], aa, bq0.y);
                ffma2(acc[i][2], aa, bq1.x);
                ffma2(acc[i][3], aa, bq1.y);
            }
        }
    }

    // ---- epilogue ----
    float add[8];
    if (EPI < 2 || addmat == nullptr) {
#pragma unroll
        for (int j = 0; j < 8; j++) {
            int n = n0 + ((j < 4) ? (4 * tx + j) : (64 + 4 * tx + (j - 4)));
            int rn = REMAP ? (((n & 3) << 8) | (n >> 2)) : n;
            float t = 0.f;
            if (b1) t += b1[rn];
            if (b2) t += b2[rn];
            add[j] = t;
        }
    }

    if (EPI >= 2) {
        const int hu0 = (n0 >> 2) + tx;
        const int hu1 = hu0 + 16;
        float pw0 = 0.f, pw1 = 0.f;
        if (EPI == 3) { pw0 = piW[hu0]; pw1 = piW[hu1]; }
#pragma unroll
        for (int i = 0; i < 8; i++) {
            int m = m0 + ((i < 4) ? (4 * ty + i) : (64 + 4 * ty + (i - 4)));
            float g[8];
#pragma unroll
            for (int j4 = 0; j4 < 4; j4++) {
                float2 f = u2f(acc[i][j4]);
                g[2 * j4] = f.x; g[2 * j4 + 1] = f.y;
            }
            if (addmat) {
                float4 p0 = *(const float4*)(addmat + (size_t)m * Gn + n0 + 4 * tx);
                float4 p1 = *(const float4*)(addmat + (size_t)m * Gn + n0 + 64 + 4 * tx);
                g[0] += p0.x; g[1] += p0.y; g[2] += p0.z; g[3] += p0.w;
                g[4] += p1.x; g[5] += p1.y; g[6] += p1.z; g[7] += p1.w;
            } else {
#pragma unroll
                for (int j = 0; j < 8; j++) g[j] += add[j];
            }
            size_t c0i = (size_t)m * Hn + hu0;
            size_t c1i = (size_t)m * Hn + hu1;
            float h0, h1;
            {
                float iv = fsig(g[0]), fv = fsig(g[1]);
                float gv = ftanh(g[2]), ov = fsig(g[3]);
                float cn = fv * cSt[c0i] + iv * gv;
                cSt[c0i] = cn;
                h0 = ov * ftanh(cn);
                C[c0i] = h0;
            }
            {
                float iv = fsig(g[4]), fv = fsig(g[5]);
                float gv = ftanh(g[6]), ov = fsig(g[7]);
                float cn = fv * cSt[c1i] + iv * gv;
                cSt[c1i] = cn;
                h1 = ov * ftanh(cn);
                C[c1i] = h1;
            }
            if (EPI == 3) {
                // reduce h·piW partial across the 16 tx lanes (one half-warp;
                // xor offsets < 16 stay within the half) — deterministic.
                float s = h0 * pw0 + h1 * pw1;
                s += __shfl_xor_sync(0xffffffffu, s, 1);
                s += __shfl_xor_sync(0xffffffffu, s, 2);
                s += __shfl_xor_sync(0xffffffffu, s, 4);
                s += __shfl_xor_sync(0xffffffffu, s, 8);
                if (tx == 0)
                    partCur[(size_t)blockIdx.x * Bsz + m] = s;
            }
        }
    } else {
#pragma unroll
        for (int i = 0; i < 8; i++) {
            int m = m0 + ((i < 4) ? (4 * ty + i) : (64 + 4 * ty + (i - 4)));
            float o[8];
#pragma unroll
            for (int j4 = 0; j4 < 4; j4++) {
                float2 f = u2f(acc[i][j4]);
                o[2 * j4]     = f.x + add[2 * j4];
                o[2 * j4 + 1] = f.y + add[2 * j4 + 1];
            }
            if (EPI == 1) {
#pragma unroll
                for (int j = 0; j < 8; j++) o[j] = fmaxf(o[j], 0.f);
            }
            *(float4*)(C + (size_t)m * N + n0 + 4 * tx)      = make_float4(o[0], o[1], o[2], o[3]);
            *(float4*)(C + (size_t)m * N + n0 + 64 + 4 * tx) = make_float4(o[4], o[5], o[6], o[7]);
        }
    }
}

// ---------------- final pi finalize (step v = Vn-1) --------------------------
__global__ void pi_final_kernel(const float* __restrict__ part,
                                const float* __restrict__ pib,
                                float* __restrict__ out, int v) {
    int m = blockIdx.x * blockDim.x + threadIdx.x;
    if (m >= Bsz) return;
    float s = pib[0];
#pragma unroll
    for (int b = 0; b < 8; b++) s += part[b * Bsz + m];
    out[(size_t)m * Vn + v] = ftanh(s);
}

// ---------------- launch ----------------------------------------------------
extern "C" void kernel_launch(void* const* d_in, const int* in_sizes, int n_in,
                              void* d_out, int out_size) {
    const float* state  = (const float*)d_in[0];   // [4096, 750]
    const float* l1_Wih = (const float*)d_in[1];   // [1024, 15]
    const float* l1_Whh = (const float*)d_in[2];   // [1024, 256]
    const float* l1_bih = (const float*)d_in[3];
    const float* l1_bhh = (const float*)d_in[4];
    const float* fc1_W  = (const float*)d_in[5];   // [1024, 256]
    const float* fc1_b  = (const float*)d_in[6];
    const float* fc2_W  = (const float*)d_in[7];   // [1024, 1024]
    const float* fc2_b  = (const float*)d_in[8];
    const float* fc3_W  = (const float*)d_in[9];   // [512, 1024]
    const float* fc3_b  = (const float*)d_in[10];
    const float* fc4_W  = (const float*)d_in[11];  // [256, 512]
    const float* fc4_b  = (const float*)d_in[12];
    const float* l2_Wih = (const float*)d_in[13];  // [1024, 271]
    const float* l2_Whh = (const float*)d_in[14];  // [1024, 256]
    const float* l2_bih = (const float*)d_in[15];
    const float* l2_bhh = (const float*)d_in[16];
    const float* pi_W   = (const float*)d_in[17];  // [1, 256]
    const float* pi_b   = (const float*)d_in[18];  // [1]
    float* out = (float*)d_out;                    // [4096, 50]

    float *h1a, *h1b, *c1, *h2a, *h2b, *c2, *m1, *m2, *m3, *m4, *pre2, *pipart;
    cudaGetSymbolAddress((void**)&h1a, g_h1a);
    cudaGetSymbolAddress((void**)&h1b, g_h1b);
    cudaGetSymbolAddress((void**)&c1,  g_c1);
    cudaGetSymbolAddress((void**)&h2a, g_h2a);
    cudaGetSymbolAddress((void**)&h2b, g_h2b);
    cudaGetSymbolAddress((void**)&c2,  g_c2);
    cudaGetSymbolAddress((void**)&m1, g_m1);
    cudaGetSymbolAddress((void**)&m2, g_m2);
    cudaGetSymbolAddress((void**)&m3, g_m3);
    cudaGetSymbolAddress((void**)&m4, g_m4);
    cudaGetSymbolAddress((void**)&pre2, g_pre2);
    cudaGetSymbolAddress((void**)&pipart, g_pipart);

    zero_states_kernel<<<(Bsz * Hn + 255) / 256, 256>>>();

    dim3 sgrid(Gn / 128, Bsz / 128);   // 8 x 32

    // ---- LSTM1 scan (fused gate GEMM + cell update), ping-pong h ----
    for (int v = 0; v < Vn; v++) {
        const float* hin  = (v & 1) ? h1b : h1a;
        float*       hout = (v & 1) ? h1a : h1b;
        gemm3<2, 1, 1><<<sgrid, 256>>>(
            hin, Hn, l1_Whh, Hn, Hn,
            state + v * Fn, Vn * Fn, l1_Wih, Fn, Fn,
            l1_bih, l1_bhh, nullptr,
            hout, Gn, c1,
            nullptr, nullptr, nullptr, nullptr, nullptr, -1);
    }
    const float* h1fin = (Vn & 1) ? h1b : h1a;

    // ---- MLP stack (relu) ----
    gemm3<1, 0, 1><<<dim3(1024 / 128, 32), 256>>>(
        h1fin, Hn, fc1_W, Hn, Hn,
        nullptr, 0, nullptr, 0, 0,
        fc1_b, nullptr, nullptr, m1, 1024, nullptr,
        nullptr, nullptr, nullptr, nullptr, nullptr, -1);
    gemm3<1, 0, 1><<<dim3(1024 / 128, 32), 256>>>(
        m1, 1024, fc2_W, 1024, 1024,
        nullptr, 0, nullptr, 0, 0,
        fc2_b, nullptr, nullptr, m2, 1024, nullptr,
        nullptr, nullptr, nullptr, nullptr, nullptr, -1);
    gemm3<1, 0, 1><<<dim3(512 / 128, 32), 256>>>(
        m2, 1024, fc3_W, 1024, 1024,
        nullptr, 0, nullptr, 0, 0,
        fc3_b, nullptr, nullptr, m3, 512, nullptr,
        nullptr, nullptr, nullptr, nullptr, nullptr, -1);
    gemm3<1, 0, 1><<<dim3(256 / 128, 32), 256>>>(
        m3, 512, fc4_W, 512, 512,
        nullptr, 0, nullptr, 0, 0,
        fc4_b, nullptr, nullptr, m4, 256, nullptr,
        nullptr, nullptr, nullptr, nullptr, nullptr, -1);

    // ---- pre2 = m4 @ Wih2[:,15:].T + bih + bhh  (REMAPPED quadrant layout) --
    gemm3<0, 1, 0><<<sgrid, 256>>>(
        m4, 256, l2_Wih + 15, 271, 256,
        nullptr, 0, nullptr, 0, 0,
        l2_bih, l2_bhh, nullptr, pre2, Gn, nullptr,
        nullptr, nullptr, nullptr, nullptr, nullptr, -1);

    // ---- LSTM2 scan (fused gate GEMM + cell update + pi head) ----
    const int PB = 8 * Bsz;   // per-parity pi-partial stride
    for (int v = 0; v < Vn; v++) {
        const float* hin  = (v & 1) ? h2b : h2a;
        float*       hout = (v & 1) ? h2a : h2b;
        gemm3<3, 1, 1><<<sgrid, 256>>>(
            hin, Hn, l2_Whh, Hn, Hn,
            state + v * Fn, Vn * Fn, l2_Wih, 271, Fn,
            nullptr, nullptr, pre2,
            hout, Gn, c2,
            pi_W, pi_b, out,
            pipart + (v & 1) * PB,
            pipart + ((v + 1) & 1) * PB,
            v - 1);
    }
    // finalize the last step's pi output
    pi_final_kernel<<<Bsz / 256, 256>>>(pipart + ((Vn - 1) & 1) * PB, pi_b, out, Vn - 1);
}